// round 1
// baseline (speedup 1.0000x reference)
#include <cuda_runtime.h>
#include <cstddef>

#define N_NODES 50000
#define N_EDGES 800000
#define BN_EPS  1e-5f

// ---------------- scratch (static device globals; allocation-free) ----------
__device__ float g_proj[(size_t)N_NODES * 128];   // h = feat @ W  (also reused at width 32)
__device__ float g_pre [(size_t)N_NODES * 128];   // aggregated pre-activation
__device__ float g_xcat[(size_t)N_NODES * 256];   // [relu(bn(pre)), pre] concat
__device__ float g_stats[256];                    // [0:128) sum, [128:256) sumsq

// ---------------- utility ---------------------------------------------------
__global__ void zero_f(float* __restrict__ p, int n) {
    int i = blockIdx.x * blockDim.x + threadIdx.x;
    if (i < n) p[i] = 0.0f;
}

// ---------------- SIMT fp32 GEMM: C[M,N] = A[M,K] @ B[K,N] ------------------
// BM=64, BN=64, BK=16, 256 threads, 4x4 per-thread tile. K assumed %16 == 0.
#define GBM 64
#define GBN 64
#define GBK 16
__global__ __launch_bounds__(256)
void gemm_kernel(const float* __restrict__ A, const float* __restrict__ B,
                 float* __restrict__ C, int M, int N, int K) {
    __shared__ float As[GBK][GBM];
    __shared__ float Bs[GBK][GBN];

    const int tid  = threadIdx.x;
    const int tx   = tid & 15;   // 16 col-groups of 4
    const int ty   = tid >> 4;   // 16 row-groups of 4
    const int row0 = blockIdx.y * GBM;
    const int col0 = blockIdx.x * GBN;

    float acc[4][4];
#pragma unroll
    for (int m = 0; m < 4; m++)
#pragma unroll
        for (int n = 0; n < 4; n++) acc[m][n] = 0.0f;

    for (int k0 = 0; k0 < K; k0 += GBK) {
        // load A tile (BM x BK) into As transposed: As[k][m]
#pragma unroll
        for (int i = tid; i < GBM * GBK; i += 256) {
            int r = i >> 4;          // 0..63
            int c = i & 15;          // 0..15
            int gr = row0 + r;
            As[c][r] = (gr < M) ? A[(size_t)gr * K + (k0 + c)] : 0.0f;
        }
        // load B tile (BK x BN): Bs[k][n]
#pragma unroll
        for (int i = tid; i < GBK * GBN; i += 256) {
            int r = i >> 6;          // 0..15
            int c = i & 63;          // 0..63
            int gc = col0 + c;
            Bs[r][c] = (gc < N) ? B[(size_t)(k0 + r) * N + gc] : 0.0f;
        }
        __syncthreads();

#pragma unroll
        for (int kk = 0; kk < GBK; kk++) {
            float4 av = *(const float4*)&As[kk][ty * 4];
            float4 bv = *(const float4*)&Bs[kk][tx * 4];
            float a[4] = {av.x, av.y, av.z, av.w};
            float b[4] = {bv.x, bv.y, bv.z, bv.w};
#pragma unroll
            for (int m = 0; m < 4; m++)
#pragma unroll
                for (int n = 0; n < 4; n++) acc[m][n] += a[m] * b[n];
        }
        __syncthreads();
    }

#pragma unroll
    for (int m = 0; m < 4; m++) {
        int gr = row0 + ty * 4 + m;
        if (gr >= M) continue;
#pragma unroll
        for (int n = 0; n < 4; n++) {
            int gc = col0 + tx * 4 + n;
            if (gc < N) C[(size_t)gr * N + gc] = acc[m][n];
        }
    }
}

// ---------------- edge aggregation (128-wide): one warp per edge ------------
// out[dst[e], :] += w[e] * h[src[e], :]   via red.global.add.v4.f32
__global__ __launch_bounds__(256)
void aggregate128(const float* __restrict__ h, const int* __restrict__ src,
                  const int* __restrict__ dst, const float* __restrict__ w,
                  float* __restrict__ out) {
    int gid  = blockIdx.x * blockDim.x + threadIdx.x;
    int e    = gid >> 5;
    int lane = gid & 31;
    if (e >= N_EDGES) return;
    int   s  = src[e];
    int   d  = dst[e];
    float wt = w[e];
    float4 v = *((const float4*)(h + (size_t)s * 128) + lane);
    v.x *= wt; v.y *= wt; v.z *= wt; v.w *= wt;
    float* op = out + (size_t)d * 128 + lane * 4;
    asm volatile("red.global.add.v4.f32 [%0], {%1,%2,%3,%4};"
                 :: "l"(op), "f"(v.x), "f"(v.y), "f"(v.z), "f"(v.w) : "memory");
}

// ---------------- edge aggregation (32-wide): 8 threads per edge ------------
__global__ __launch_bounds__(256)
void aggregate32(const float* __restrict__ h, const int* __restrict__ src,
                 const int* __restrict__ dst, const float* __restrict__ w,
                 float* __restrict__ out) {
    int gid  = blockIdx.x * blockDim.x + threadIdx.x;
    int e    = gid >> 3;
    int lane = gid & 7;
    if (e >= N_EDGES) return;
    int   s  = src[e];
    int   d  = dst[e];
    float wt = w[e];
    float4 v = *((const float4*)(h + (size_t)s * 32) + lane);
    v.x *= wt; v.y *= wt; v.z *= wt; v.w *= wt;
    float* op = out + (size_t)d * 32 + lane * 4;
    asm volatile("red.global.add.v4.f32 [%0], {%1,%2,%3,%4};"
                 :: "l"(op), "f"(v.x), "f"(v.y), "f"(v.z), "f"(v.w) : "memory");
}

// ---------------- BN stats: column sums / sumsq over N rows (C=128) ---------
__global__ __launch_bounds__(128)
void bn_stats(const float* __restrict__ pre, float* __restrict__ stats) {
    int c = threadIdx.x;              // 0..127
    float s = 0.0f, s2 = 0.0f;
    for (int r = blockIdx.x; r < N_NODES; r += gridDim.x) {
        float v = pre[(size_t)r * 128 + c];
        s  += v;
        s2 += v * v;
    }
    atomicAdd(&stats[c], s);
    atomicAdd(&stats[128 + c], s2);
}

// ---------------- BN apply + ReLU + skip-concat -----------------------------
// xcat[r, 0:128]   = relu(bn(pre[r,:]))
// xcat[r, 128:256] = pre[r,:]
__global__ __launch_bounds__(256)
void bn_apply_concat(const float* __restrict__ pre, const float* __restrict__ stats,
                     const float* __restrict__ gamma, const float* __restrict__ beta,
                     float* __restrict__ xcat) {
    int idx = blockIdx.x * blockDim.x + threadIdx.x;
    if (idx >= N_NODES * 128) return;
    int c = idx & 127;
    int r = idx >> 7;
    const float invN = 1.0f / (float)N_NODES;
    float mu  = stats[c] * invN;
    float var = stats[128 + c] * invN - mu * mu;
    float inv = rsqrtf(var + BN_EPS);
    float v   = pre[idx];
    float bn  = (v - mu) * inv * gamma[c] + beta[c];
    float h   = bn > 0.0f ? bn : 0.0f;
    xcat[(size_t)r * 256 + c]       = h;
    xcat[(size_t)r * 256 + 128 + c] = v;
}

// ---------------- launch -----------------------------------------------------
extern "C" void kernel_launch(void* const* d_in, const int* in_sizes, int n_in,
                              void* d_out, int out_size) {
    const float* x      = (const float*)d_in[0];
    const int*   src    = (const int*)  d_in[1];
    const int*   dst    = (const int*)  d_in[2];
    const float* ew     = (const float*)d_in[3];
    const float* W0     = (const float*)d_in[4];
    const float* W1     = (const float*)d_in[5];
    const float* W2     = (const float*)d_in[6];
    const float* gamma0 = (const float*)d_in[7];
    const float* beta0  = (const float*)d_in[8];
    const float* gamma1 = (const float*)d_in[9];
    const float* beta1  = (const float*)d_in[10];
    float* out = (float*)d_out;

    float *proj, *pre, *xcat, *stats;
    cudaGetSymbolAddress((void**)&proj,  g_proj);
    cudaGetSymbolAddress((void**)&pre,   g_pre);
    cudaGetSymbolAddress((void**)&xcat,  g_xcat);
    cudaGetSymbolAddress((void**)&stats, g_stats);

    const dim3 gemmGrid128(2, (N_NODES + GBM - 1) / GBM);
    const dim3 gemmGrid32 (1, (N_NODES + GBM - 1) / GBM);
    const int nPre   = N_NODES * 128;
    const int zbPre  = (nPre + 255) / 256;
    const int aggB128 = (N_EDGES * 32) / 256;   // 100000
    const int aggB32  = (N_EDGES * 8)  / 256;   // 25000
    const int nOut   = N_NODES * 32;
    const int zbOut  = (nOut + 255) / 256;

    // ---- layer 0 ----
    gemm_kernel<<<gemmGrid128, 256>>>(x, W0, proj, N_NODES, 128, 256);
    zero_f<<<zbPre, 256>>>(pre, nPre);
    zero_f<<<1, 256>>>(stats, 256);
    aggregate128<<<aggB128, 256>>>(proj, src, dst, ew, pre);
    bn_stats<<<512, 128>>>(pre, stats);
    bn_apply_concat<<<zbPre, 256>>>(pre, stats, gamma0, beta0, xcat);

    // ---- layer 1 ----
    gemm_kernel<<<gemmGrid128, 256>>>(xcat, W1, proj, N_NODES, 128, 256);
    zero_f<<<zbPre, 256>>>(pre, nPre);
    zero_f<<<1, 256>>>(stats, 256);
    aggregate128<<<aggB128, 256>>>(proj, src, dst, ew, pre);
    bn_stats<<<512, 128>>>(pre, stats);
    bn_apply_concat<<<zbPre, 256>>>(pre, stats, gamma1, beta1, xcat);

    // ---- output layer ----
    gemm_kernel<<<gemmGrid32, 256>>>(xcat, W2, proj, N_NODES, 32, 256);
    zero_f<<<zbOut, 256>>>(out, nOut);
    aggregate32<<<aggB32, 256>>>(proj, src, dst, ew, out);
}

// round 3
// speedup vs baseline: 1.4557x; 1.4557x over previous
#include <cuda_runtime.h>
#include <cuda_bf16.h>
#include <cstdint>
#include <cstddef>

#define N_NODES 50000
#define N_EDGES 800000
#define BN_EPS  1e-5f

// ---------------- scratch (static device globals; allocation-free) ----------
__device__ __nv_bfloat16 g_xhi[(size_t)N_NODES * 256];
__device__ __nv_bfloat16 g_xlo[(size_t)N_NODES * 256];
__device__ __nv_bfloat16 g_whi[256 * 128];          // transposed weights [N][K]
__device__ __nv_bfloat16 g_wlo[256 * 128];
__device__ float g_proj[(size_t)N_NODES * 128];     // GEMM output (also width 32)
__device__ float g_pre [(size_t)N_NODES * 128];     // aggregated pre-activation
__device__ float g_stats[256];                      // [0:128) sum, [128:256) sumsq

// ---------------- mma.sync wrapper (bf16 in, fp32 accum) ---------------------
__device__ __forceinline__ void mma16816(float* d, const uint32_t* a, const uint32_t* b) {
    asm volatile(
        "mma.sync.aligned.m16n8k16.row.col.f32.bf16.bf16.f32 "
        "{%0,%1,%2,%3}, {%4,%5,%6,%7}, {%8,%9}, {%0,%1,%2,%3};"
        : "+f"(d[0]), "+f"(d[1]), "+f"(d[2]), "+f"(d[3])
        : "r"(a[0]), "r"(a[1]), "r"(a[2]), "r"(a[3]), "r"(b[0]), "r"(b[1]));
}

// ---------------- conversion kernels ----------------------------------------
__global__ __launch_bounds__(256)
void convert_x(const float* __restrict__ x, __nv_bfloat16* __restrict__ hi,
               __nv_bfloat16* __restrict__ lo, int n) {
    int i = blockIdx.x * blockDim.x + threadIdx.x;
    if (i >= n) return;
    float v = x[i];
    __nv_bfloat16 h = __float2bfloat16(v);
    hi[i] = h;
    lo[i] = __float2bfloat16(v - __bfloat162float(h));
}

// W [K=256, N] -> Wt_hi/lo [N, 256] (transposed, K-major)
__global__ __launch_bounds__(256)
void convert_w(const float* __restrict__ W, __nv_bfloat16* __restrict__ hi,
               __nv_bfloat16* __restrict__ lo, int N) {
    int i = blockIdx.x * blockDim.x + threadIdx.x;   // i = n*256 + k
    if (i >= N * 256) return;
    int n = i >> 8, k = i & 255;
    float v = W[(size_t)k * N + n];
    __nv_bfloat16 h = __float2bfloat16(v);
    hi[i] = h;
    lo[i] = __float2bfloat16(v - __bfloat162float(h));
}

// ---------------- mma.sync GEMM: C[M,NT] = A[M,256] @ Wt[NT,256]^T -----------
// A hi/lo bf16 [M,256] row-major; Wt hi/lo bf16 [NT,256] (n-major, k contiguous).
// CTA: 128 x NT tile, 256 threads = 8 warps (4 in m, 2 in n).
// Warp tile: 32 x NT/2. BK = 64. smem row stride 72 bf16 (144B) — conflict-free.
template <int NT>
__global__ __launch_bounds__(256, 1)
void gemm_mma(const __nv_bfloat16* __restrict__ Ahi, const __nv_bfloat16* __restrict__ Alo,
              const __nv_bfloat16* __restrict__ Bhi, const __nv_bfloat16* __restrict__ Blo,
              float* __restrict__ C, int M) {
    constexpr int KS   = 72;                // smem stride in elements
    constexpr int ROWB = KS * 2;            // 144 bytes per row
    constexpr int WNT  = NT / 16;           // n-tiles (8 cols) per warp
    extern __shared__ char sm[];
    char* sAhi = sm;
    char* sAlo = sAhi + 128 * ROWB;
    char* sBhi = sAlo + 128 * ROWB;
    char* sBlo = sBhi + NT * ROWB;

    const int tid  = threadIdx.x;
    const int wid  = tid >> 5;
    const int lane = tid & 31;
    const int wm   = wid & 3;               // warp m index (0..3)
    const int wn   = wid >> 2;              // warp n index (0..1)
    const int m0   = blockIdx.x * 128;
    const int r    = lane >> 2;             // 0..7
    const int c2   = (lane & 3) * 2;        // 0,2,4,6

    const uint4* Ahi4 = (const uint4*)Ahi;
    const uint4* Alo4 = (const uint4*)Alo;
    const uint4* Bhi4 = (const uint4*)Bhi;
    const uint4* Blo4 = (const uint4*)Blo;
    const uint4  z4   = make_uint4(0, 0, 0, 0);

    float acc[2][WNT][4];
#pragma unroll
    for (int mt = 0; mt < 2; mt++)
#pragma unroll
        for (int j = 0; j < WNT; j++)
#pragma unroll
            for (int q = 0; q < 4; q++) acc[mt][j][q] = 0.0f;

    for (int ch = 0; ch < 4; ch++) {
        const int kg8 = ch * 8;              // global k offset in uint4 units (64 bf16)
        // ---- stage A tile: 128 rows x 64 bf16 (8 uint4/row) ----
#pragma unroll
        for (int j = 0; j < 4; j++) {
            int i  = tid + j * 256;          // 0..1023
            int rr = i >> 3, c8 = i & 7;
            int gr = m0 + rr;
            uint4 vh = z4, vl = z4;
            if (gr < M) {
                size_t g = (size_t)gr * 32 + kg8 + c8;
                vh = Ahi4[g]; vl = Alo4[g];
            }
            *(uint4*)(sAhi + rr * ROWB + c8 * 16) = vh;
            *(uint4*)(sAlo + rr * ROWB + c8 * 16) = vl;
        }
        // ---- stage B tile: NT rows x 64 bf16 ----
#pragma unroll
        for (int j = 0; j < NT / 32; j++) {
            int i  = tid + j * 256;
            int rr = i >> 3, c8 = i & 7;
            size_t g = (size_t)rr * 32 + kg8 + c8;
            *(uint4*)(sBhi + rr * ROWB + c8 * 16) = Bhi4[g];
            *(uint4*)(sBlo + rr * ROWB + c8 * 16) = Blo4[g];
        }
        __syncthreads();

#pragma unroll
        for (int ks = 0; ks < 4; ks++) {
            const int k0 = ks * 16;
            // ---- A fragments (2 m-tiles, hi+lo) ----
            uint32_t ah[2][4], al[2][4];
#pragma unroll
            for (int mt = 0; mt < 2; mt++) {
                int row = wm * 32 + mt * 16;
                const char* p0 = sAhi + (row + r)     * ROWB;
                const char* p1 = sAhi + (row + r + 8) * ROWB;
                ah[mt][0] = *(const uint32_t*)(p0 + (k0 + c2)     * 2);
                ah[mt][1] = *(const uint32_t*)(p1 + (k0 + c2)     * 2);
                ah[mt][2] = *(const uint32_t*)(p0 + (k0 + c2 + 8) * 2);
                ah[mt][3] = *(const uint32_t*)(p1 + (k0 + c2 + 8) * 2);
                const char* q0 = sAlo + (row + r)     * ROWB;
                const char* q1 = sAlo + (row + r + 8) * ROWB;
                al[mt][0] = *(const uint32_t*)(q0 + (k0 + c2)     * 2);
                al[mt][1] = *(const uint32_t*)(q1 + (k0 + c2)     * 2);
                al[mt][2] = *(const uint32_t*)(q0 + (k0 + c2 + 8) * 2);
                al[mt][3] = *(const uint32_t*)(q1 + (k0 + c2 + 8) * 2);
            }
            // ---- per n-tile: load B frags, 6 MMAs ----
#pragma unroll
            for (int j = 0; j < WNT; j++) {
                int n = wn * (NT / 2) + j * 8 + r;
                const char* pb = sBhi + n * ROWB;
                const char* qb = sBlo + n * ROWB;
                uint32_t bh[2], bl[2];
                bh[0] = *(const uint32_t*)(pb + (k0 + c2)     * 2);
                bh[1] = *(const uint32_t*)(pb + (k0 + c2 + 8) * 2);
                bl[0] = *(const uint32_t*)(qb + (k0 + c2)     * 2);
                bl[1] = *(const uint32_t*)(qb + (k0 + c2 + 8) * 2);
#pragma unroll
                for (int mt = 0; mt < 2; mt++) {
                    mma16816(acc[mt][j], ah[mt], bh);
                    mma16816(acc[mt][j], ah[mt], bl);
                    mma16816(acc[mt][j], al[mt], bh);
                }
            }
        }
        __syncthreads();
    }

    // ---- epilogue ----
#pragma unroll
    for (int mt = 0; mt < 2; mt++) {
        int row0 = m0 + wm * 32 + mt * 16 + r;
#pragma unroll
        for (int j = 0; j < WNT; j++) {
            int col = wn * (NT / 2) + j * 8 + c2;
            if (row0 < M)
                *(float2*)&C[(size_t)row0 * NT + col] = make_float2(acc[mt][j][0], acc[mt][j][1]);
            if (row0 + 8 < M)
                *(float2*)&C[(size_t)(row0 + 8) * NT + col] = make_float2(acc[mt][j][2], acc[mt][j][3]);
        }
    }
}

// ---------------- utility ----------------------------------------------------
__global__ void zero_f(float* __restrict__ p, int n) {
    int i = blockIdx.x * blockDim.x + threadIdx.x;
    if (i < n) p[i] = 0.0f;
}

// ---------------- edge aggregation (128-wide): one warp per edge -------------
__global__ __launch_bounds__(256)
void aggregate128(const float* __restrict__ h, const int* __restrict__ src,
                  const int* __restrict__ dst, const float* __restrict__ w,
                  float* __restrict__ out) {
    int gid  = blockIdx.x * blockDim.x + threadIdx.x;
    int e    = gid >> 5;
    int lane = gid & 31;
    if (e >= N_EDGES) return;
    int   s  = src[e];
    int   d  = dst[e];
    float wt = w[e];
    float4 v = *((const float4*)(h + (size_t)s * 128) + lane);
    v.x *= wt; v.y *= wt; v.z *= wt; v.w *= wt;
    float* op = out + (size_t)d * 128 + lane * 4;
    asm volatile("red.global.add.v4.f32 [%0], {%1,%2,%3,%4};"
                 :: "l"(op), "f"(v.x), "f"(v.y), "f"(v.z), "f"(v.w) : "memory");
}

__global__ __launch_bounds__(256)
void aggregate32(const float* __restrict__ h, const int* __restrict__ src,
                 const int* __restrict__ dst, const float* __restrict__ w,
                 float* __restrict__ out) {
    int gid  = blockIdx.x * blockDim.x + threadIdx.x;
    int e    = gid >> 3;
    int lane = gid & 7;
    if (e >= N_EDGES) return;
    int   s  = src[e];
    int   d  = dst[e];
    float wt = w[e];
    float4 v = *((const float4*)(h + (size_t)s * 32) + lane);
    v.x *= wt; v.y *= wt; v.z *= wt; v.w *= wt;
    float* op = out + (size_t)d * 32 + lane * 4;
    asm volatile("red.global.add.v4.f32 [%0], {%1,%2,%3,%4};"
                 :: "l"(op), "f"(v.x), "f"(v.y), "f"(v.z), "f"(v.w) : "memory");
}

// ---------------- BN stats ----------------------------------------------------
__global__ __launch_bounds__(128)
void bn_stats(const float* __restrict__ pre, float* __restrict__ stats) {
    int c = threadIdx.x;
    float s = 0.0f, s2 = 0.0f;
    for (int r = blockIdx.x; r < N_NODES; r += gridDim.x) {
        float v = pre[(size_t)r * 128 + c];
        s += v; s2 += v * v;
    }
    atomicAdd(&stats[c], s);
    atomicAdd(&stats[128 + c], s2);
}

// ---------------- BN apply + ReLU + concat -> bf16 hi/lo pair ----------------
__global__ __launch_bounds__(256)
void bn_apply_concat(const float* __restrict__ pre, const float* __restrict__ stats,
                     const float* __restrict__ gamma, const float* __restrict__ beta,
                     __nv_bfloat16* __restrict__ xhi, __nv_bfloat16* __restrict__ xlo) {
    int idx = blockIdx.x * blockDim.x + threadIdx.x;
    if (idx >= N_NODES * 128) return;
    int c = idx & 127;
    int r = idx >> 7;
    const float invN = 1.0f / (float)N_NODES;
    float mu  = stats[c] * invN;
    float var = stats[128 + c] * invN - mu * mu;
    float inv = rsqrtf(var + BN_EPS);
    float v   = pre[idx];
    float bn  = (v - mu) * inv * gamma[c] + beta[c];
    float hv  = bn > 0.0f ? bn : 0.0f;

    size_t o0 = (size_t)r * 256 + c;        // relu(bn) half
    __nv_bfloat16 h0 = __float2bfloat16(hv);
    xhi[o0] = h0;
    xlo[o0] = __float2bfloat16(hv - __bfloat162float(h0));

    size_t o1 = o0 + 128;                   // skip half (raw pre)
    __nv_bfloat16 h1 = __float2bfloat16(v);
    xhi[o1] = h1;
    xlo[o1] = __float2bfloat16(v - __bfloat162float(h1));
}

// ---------------- launch ------------------------------------------------------
extern "C" void kernel_launch(void* const* d_in, const int* in_sizes, int n_in,
                              void* d_out, int out_size) {
    const float* x      = (const float*)d_in[0];
    const int*   src    = (const int*)  d_in[1];
    const int*   dst    = (const int*)  d_in[2];
    const float* ew     = (const float*)d_in[3];
    const float* W0     = (const float*)d_in[4];
    const float* W1     = (const float*)d_in[5];
    const float* W2     = (const float*)d_in[6];
    const float* gamma0 = (const float*)d_in[7];
    const float* beta0  = (const float*)d_in[8];
    const float* gamma1 = (const float*)d_in[9];
    const float* beta1  = (const float*)d_in[10];
    float* out = (float*)d_out;

    __nv_bfloat16 *xhi, *xlo, *whi, *wlo;
    float *proj, *pre, *stats;
    cudaGetSymbolAddress((void**)&xhi,   g_xhi);
    cudaGetSymbolAddress((void**)&xlo,   g_xlo);
    cudaGetSymbolAddress((void**)&whi,   g_whi);
    cudaGetSymbolAddress((void**)&wlo,   g_wlo);
    cudaGetSymbolAddress((void**)&proj,  g_proj);
    cudaGetSymbolAddress((void**)&pre,   g_pre);
    cudaGetSymbolAddress((void**)&stats, g_stats);

    const int smem128 = (128 * 2 + 128 * 2) * 144;   // 73728
    const int smem32  = (128 * 2 + 32 * 2)  * 144;   // 46080
    cudaFuncSetAttribute(gemm_mma<128>, cudaFuncAttributeMaxDynamicSharedMemorySize, smem128);
    cudaFuncSetAttribute(gemm_mma<32>,  cudaFuncAttributeMaxDynamicSharedMemorySize, smem32);

    const int nX     = N_NODES * 256;
    const int nPre   = N_NODES * 128;
    const int zbPre  = (nPre + 255) / 256;
    const int aggB128 = (N_EDGES * 32) / 256;
    const int aggB32  = (N_EDGES * 8)  / 256;
    const int nOut   = N_NODES * 32;
    const int zbOut  = (nOut + 255) / 256;
    const int mTiles = (N_NODES + 127) / 128;    // 391

    // ---- layer 0 ----
    convert_x<<<(nX + 255) / 256, 256>>>(x, xhi, xlo, nX);
    convert_w<<<(128 * 256 + 255) / 256, 256>>>(W0, whi, wlo, 128);
    gemm_mma<128><<<mTiles, 256, smem128>>>(xhi, xlo, whi, wlo, proj, N_NODES);
    zero_f<<<zbPre, 256>>>(pre, nPre);
    zero_f<<<1, 256>>>(stats, 256);
    aggregate128<<<aggB128, 256>>>(proj, src, dst, ew, pre);
    bn_stats<<<512, 128>>>(pre, stats);
    bn_apply_concat<<<zbPre, 256>>>(pre, stats, gamma0, beta0, xhi, xlo);

    // ---- layer 1 ----
    convert_w<<<(128 * 256 + 255) / 256, 256>>>(W1, whi, wlo, 128);
    gemm_mma<128><<<mTiles, 256, smem128>>>(xhi, xlo, whi, wlo, proj, N_NODES);
    zero_f<<<zbPre, 256>>>(pre, nPre);
    zero_f<<<1, 256>>>(stats, 256);
    aggregate128<<<aggB128, 256>>>(proj, src, dst, ew, pre);
    bn_stats<<<512, 128>>>(pre, stats);
    bn_apply_concat<<<zbPre, 256>>>(pre, stats, gamma1, beta1, xhi, xlo);

    // ---- output layer (N=32) ----
    convert_w<<<(32 * 256 + 255) / 256, 256>>>(W2, whi, wlo, 32);
    gemm_mma<32><<<mTiles, 256, smem32>>>(xhi, xlo, whi, wlo, proj, N_NODES);
    zero_f<<<zbOut, 256>>>(out, nOut);
    aggregate32<<<aggB32, 256>>>(proj, src, dst, ew, out);
}

// round 4
// speedup vs baseline: 1.6807x; 1.1545x over previous
#include <cuda_runtime.h>
#include <cuda_bf16.h>
#include <cstdint>
#include <cstddef>

#define N_NODES 50000
#define N_EDGES 800000
#define BN_EPS  1e-5f

// ---------------- scratch (static device globals; allocation-free) ----------
__device__ __nv_bfloat16 g_xhi[(size_t)N_NODES * 256];
__device__ __nv_bfloat16 g_xlo[(size_t)N_NODES * 256];
__device__ __nv_bfloat16 g_whi[256 * 128];          // transposed weights [N][K]
__device__ __nv_bfloat16 g_wlo[256 * 128];
__device__ float g_proj[(size_t)N_NODES * 128];     // GEMM output (also width 32)
__device__ float g_pre [(size_t)N_NODES * 128];     // aggregated pre-activation
__device__ float g_stats[256];                      // [0:128) sum, [128:256) sumsq

// ---------------- asm helpers ------------------------------------------------
__device__ __forceinline__ void mma16816(float* d, const uint32_t* a, const uint32_t* b) {
    asm volatile(
        "mma.sync.aligned.m16n8k16.row.col.f32.bf16.bf16.f32 "
        "{%0,%1,%2,%3}, {%4,%5,%6,%7}, {%8,%9}, {%0,%1,%2,%3};"
        : "+f"(d[0]), "+f"(d[1]), "+f"(d[2]), "+f"(d[3])
        : "r"(a[0]), "r"(a[1]), "r"(a[2]), "r"(a[3]), "r"(b[0]), "r"(b[1]));
}
__device__ __forceinline__ uint32_t smem_u32(const void* p) {
    uint32_t a;
    asm("{ .reg .u64 t; cvta.to.shared.u64 t, %1; cvt.u32.u64 %0, t; }" : "=r"(a) : "l"(p));
    return a;
}
__device__ __forceinline__ void cpasync16(uint32_t dst, const void* src, int src_sz) {
    asm volatile("cp.async.ca.shared.global [%0], [%1], 16, %2;"
                 :: "r"(dst), "l"(src), "r"(src_sz));
}
#define CP_COMMIT() asm volatile("cp.async.commit_group;" ::: "memory")
__device__ __forceinline__ void redg_v4(float* p, float4 v) {
    asm volatile("red.global.add.v4.f32 [%0], {%1,%2,%3,%4};"
                 :: "l"(p), "f"(v.x), "f"(v.y), "f"(v.z), "f"(v.w) : "memory");
}

// ---------------- conversion kernels ----------------------------------------
__global__ __launch_bounds__(256)
void convert_x4(const float* __restrict__ x, __nv_bfloat16* __restrict__ hi,
                __nv_bfloat16* __restrict__ lo, int n4) {
    int i = blockIdx.x * blockDim.x + threadIdx.x;
    if (i >= n4) return;
    float4 v = ((const float4*)x)[i];
    __nv_bfloat16 h0 = __float2bfloat16(v.x), h1 = __float2bfloat16(v.y);
    __nv_bfloat16 h2 = __float2bfloat16(v.z), h3 = __float2bfloat16(v.w);
    __nv_bfloat162 a = {h0, h1}, b = {h2, h3};
    ((uint2*)hi)[i] = make_uint2(*(uint32_t*)&a, *(uint32_t*)&b);
    __nv_bfloat162 c = {__float2bfloat16(v.x - __bfloat162float(h0)),
                        __float2bfloat16(v.y - __bfloat162float(h1))};
    __nv_bfloat162 d = {__float2bfloat16(v.z - __bfloat162float(h2)),
                        __float2bfloat16(v.w - __bfloat162float(h3))};
    ((uint2*)lo)[i] = make_uint2(*(uint32_t*)&c, *(uint32_t*)&d);
}

// W [K=256, N] -> Wt_hi/lo [N, 256] (transposed, K-major)
__global__ __launch_bounds__(256)
void convert_w(const float* __restrict__ W, __nv_bfloat16* __restrict__ hi,
               __nv_bfloat16* __restrict__ lo, int N) {
    int i = blockIdx.x * blockDim.x + threadIdx.x;
    if (i >= N * 256) return;
    int n = i >> 8, k = i & 255;
    float v = W[(size_t)k * N + n];
    __nv_bfloat16 h = __float2bfloat16(v);
    hi[i] = h;
    lo[i] = __float2bfloat16(v - __bfloat162float(h));
}

// ---------------- pipelined mma.sync GEMM ------------------------------------
// C[M,NT] = A[M,256] @ Wt[NT,256]^T. CTA 128xNT, 8 warps (4m x 2n).
// BK=32, 2-stage cp.async. smem row stride 96B (conflict-free frag reads).
template <int NT>
__device__ __forceinline__ void gload(uint32_t sbase, const uint4* Ahi4, const uint4* Alo4,
                                      const uint4* Bhi4, const uint4* Blo4,
                                      int m0, int M, int ch, int tid) {
    const uint32_t sAhi = sbase;
    const uint32_t sAlo = sbase + 128 * 96;
    const uint32_t sBhi = sbase + 256 * 96;
    const uint32_t sBlo = sbase + 256 * 96 + NT * 96;
#pragma unroll
    for (int j = 0; j < 2; j++) {               // A: 128 rows x 4 uint4
        int i   = tid + j * 256;
        int row = i >> 2, c4 = i & 3;
        int gr  = m0 + row;
        int ok  = (gr < M) ? 16 : 0;
        size_t g = (size_t)(ok ? gr : 0) * 32 + ch * 4 + c4;
        cpasync16(sAhi + row * 96 + c4 * 16, Ahi4 + g, ok);
        cpasync16(sAlo + row * 96 + c4 * 16, Alo4 + g, ok);
    }
#pragma unroll
    for (int j = 0; j < (NT * 4 + 255) / 256; j++) {   // B: NT rows x 4 uint4
        int i = tid + j * 256;
        if (i < NT * 4) {
            int row = i >> 2, c4 = i & 3;
            size_t g = (size_t)row * 32 + ch * 4 + c4;
            cpasync16(sBhi + row * 96 + c4 * 16, Bhi4 + g, 16);
            cpasync16(sBlo + row * 96 + c4 * 16, Blo4 + g, 16);
        }
    }
}

template <int NT>
__global__ __launch_bounds__(256, 2)
void gemm_mma2(const __nv_bfloat16* __restrict__ Ahi, const __nv_bfloat16* __restrict__ Alo,
               const __nv_bfloat16* __restrict__ Bhi, const __nv_bfloat16* __restrict__ Blo,
               float* __restrict__ C, int M) {
    constexpr int WNT   = NT / 16;
    constexpr int STAGE = (256 + 2 * NT) * 96;
    extern __shared__ char sm[];
    const uint32_t smu = smem_u32(sm);

    const int tid  = threadIdx.x;
    const int wid  = tid >> 5;
    const int lane = tid & 31;
    const int wm   = wid & 3;
    const int wn   = wid >> 2;
    const int m0   = blockIdx.x * 128;
    const int r    = lane >> 2;
    const int c2   = (lane & 3) * 2;

    const uint4* Ahi4 = (const uint4*)Ahi;
    const uint4* Alo4 = (const uint4*)Alo;
    const uint4* Bhi4 = (const uint4*)Bhi;
    const uint4* Blo4 = (const uint4*)Blo;

    float acc[2][WNT][4];
#pragma unroll
    for (int mt = 0; mt < 2; mt++)
#pragma unroll
        for (int j = 0; j < WNT; j++)
#pragma unroll
            for (int q = 0; q < 4; q++) acc[mt][j][q] = 0.0f;

    gload<NT>(smu, Ahi4, Alo4, Bhi4, Blo4, m0, M, 0, tid);
    CP_COMMIT();

    for (int ch = 0; ch < 8; ch++) {
        if (ch < 7) {
            gload<NT>(smu + ((ch + 1) & 1) * STAGE, Ahi4, Alo4, Bhi4, Blo4, m0, M, ch + 1, tid);
            CP_COMMIT();
            asm volatile("cp.async.wait_group 1;" ::: "memory");
        } else {
            asm volatile("cp.async.wait_group 0;" ::: "memory");
        }
        __syncthreads();

        const char* st   = sm + (ch & 1) * STAGE;
        const char* sAhi = st;
        const char* sAlo = st + 128 * 96;
        const char* sBhi = st + 256 * 96;
        const char* sBlo = st + 256 * 96 + NT * 96;

#pragma unroll
        for (int ks = 0; ks < 2; ks++) {
            const int k0 = ks * 16;
            uint32_t ah[2][4], al[2][4];
#pragma unroll
            for (int mt = 0; mt < 2; mt++) {
                int row = wm * 32 + mt * 16;
                const char* p0 = sAhi + (row + r)     * 96 + (k0 + c2) * 2;
                const char* p1 = sAhi + (row + r + 8) * 96 + (k0 + c2) * 2;
                ah[mt][0] = *(const uint32_t*)p0;
                ah[mt][1] = *(const uint32_t*)p1;
                ah[mt][2] = *(const uint32_t*)(p0 + 16);
                ah[mt][3] = *(const uint32_t*)(p1 + 16);
                const char* q0 = sAlo + (row + r)     * 96 + (k0 + c2) * 2;
                const char* q1 = sAlo + (row + r + 8) * 96 + (k0 + c2) * 2;
                al[mt][0] = *(const uint32_t*)q0;
                al[mt][1] = *(const uint32_t*)q1;
                al[mt][2] = *(const uint32_t*)(q0 + 16);
                al[mt][3] = *(const uint32_t*)(q1 + 16);
            }
#pragma unroll
            for (int j = 0; j < WNT; j++) {
                int n = wn * (NT / 2) + j * 8 + r;
                const char* pb = sBhi + n * 96 + (k0 + c2) * 2;
                const char* qb = sBlo + n * 96 + (k0 + c2) * 2;
                uint32_t bh[2], bl[2];
                bh[0] = *(const uint32_t*)pb;
                bh[1] = *(const uint32_t*)(pb + 16);
                bl[0] = *(const uint32_t*)qb;
                bl[1] = *(const uint32_t*)(qb + 16);
#pragma unroll
                for (int mt = 0; mt < 2; mt++) {
                    mma16816(acc[mt][j], ah[mt], bh);
                    mma16816(acc[mt][j], ah[mt], bl);
                    mma16816(acc[mt][j], al[mt], bh);
                }
            }
        }
        __syncthreads();
    }

#pragma unroll
    for (int mt = 0; mt < 2; mt++) {
        int row0 = m0 + wm * 32 + mt * 16 + r;
#pragma unroll
        for (int j = 0; j < WNT; j++) {
            int col = wn * (NT / 2) + j * 8 + c2;
            if (row0 < M)
                *(float2*)&C[(size_t)row0 * NT + col] = make_float2(acc[mt][j][0], acc[mt][j][1]);
            if (row0 + 8 < M)
                *(float2*)&C[(size_t)(row0 + 8) * NT + col] = make_float2(acc[mt][j][2], acc[mt][j][3]);
        }
    }
}

// ---------------- utility ----------------------------------------------------
__global__ __launch_bounds__(256)
void zero4(float4* __restrict__ p, int n4) {
    int i = blockIdx.x * blockDim.x + threadIdx.x;
    if (i < n4) p[i] = make_float4(0.f, 0.f, 0.f, 0.f);
}
__global__ void zero_f(float* __restrict__ p, int n) {
    int i = blockIdx.x * blockDim.x + threadIdx.x;
    if (i < n) p[i] = 0.0f;
}

// ---------------- edge aggregation -------------------------------------------
__global__ __launch_bounds__(256)
void aggregate128(const float* __restrict__ h, const int* __restrict__ src,
                  const int* __restrict__ dst, const float* __restrict__ w,
                  float* __restrict__ out) {
    int gid  = blockIdx.x * blockDim.x + threadIdx.x;
    int e    = gid >> 5;
    int lane = gid & 31;
    if (e >= N_EDGES) return;
    int   s  = src[e];
    int   d  = dst[e];
    float wt = w[e];
    float4 v = *((const float4*)(h + (size_t)s * 128) + lane);
    v.x *= wt; v.y *= wt; v.z *= wt; v.w *= wt;
    redg_v4(out + (size_t)d * 128 + lane * 4, v);
}

__global__ __launch_bounds__(256)
void aggregate32(const float* __restrict__ h, const int* __restrict__ src,
                 const int* __restrict__ dst, const float* __restrict__ w,
                 float* __restrict__ out) {
    int gid  = blockIdx.x * blockDim.x + threadIdx.x;
    int e    = gid >> 3;
    int lane = gid & 7;
    if (e >= N_EDGES) return;
    int   s  = src[e];
    int   d  = dst[e];
    float wt = w[e];
    float4 v = *((const float4*)(h + (size_t)s * 32) + lane);
    v.x *= wt; v.y *= wt; v.z *= wt; v.w *= wt;
    redg_v4(out + (size_t)d * 32 + lane * 4, v);
}

// ---------------- BN stats (vectorized, block-reduced) ------------------------
__global__ __launch_bounds__(256)
void bn_stats2(const float* __restrict__ pre, float* __restrict__ stats) {
    int tid = threadIdx.x;
    int cg  = tid & 31;        // column group (4 cols)
    int rg  = tid >> 5;        // row group 0..7
    int c   = cg * 4;
    float4 s = make_float4(0.f, 0.f, 0.f, 0.f);
    float4 q = make_float4(0.f, 0.f, 0.f, 0.f);
    for (int r = blockIdx.x * 8 + rg; r < N_NODES; r += gridDim.x * 8) {
        float4 v = *(const float4*)(pre + (size_t)r * 128 + c);
        s.x += v.x; s.y += v.y; s.z += v.z; s.w += v.w;
        q.x += v.x * v.x; q.y += v.y * v.y; q.z += v.z * v.z; q.w += v.w * v.w;
    }
    __shared__ float shS[8][128], shQ[8][128];
    *(float4*)&shS[rg][c] = s;
    *(float4*)&shQ[rg][c] = q;
    __syncthreads();
    if (tid < 32) {
        int cc = tid * 4;
        float4 S = make_float4(0.f, 0.f, 0.f, 0.f);
        float4 Q = make_float4(0.f, 0.f, 0.f, 0.f);
#pragma unroll
        for (int g = 0; g < 8; g++) {
            float4 a = *(float4*)&shS[g][cc];
            float4 b = *(float4*)&shQ[g][cc];
            S.x += a.x; S.y += a.y; S.z += a.z; S.w += a.w;
            Q.x += b.x; Q.y += b.y; Q.z += b.z; Q.w += b.w;
        }
        redg_v4(stats + cc, S);
        redg_v4(stats + 128 + cc, Q);
    }
}

// ---------------- BN apply + ReLU + concat -> bf16; zeroes pre in place -------
__global__ __launch_bounds__(256)
void bn_apply_concat4(const float* __restrict__ pre, const float* __restrict__ stats,
                      const float* __restrict__ gamma, const float* __restrict__ beta,
                      __nv_bfloat16* __restrict__ xhi, __nv_bfloat16* __restrict__ xlo,
                      float* __restrict__ prez) {
    int idx4 = blockIdx.x * blockDim.x + threadIdx.x;
    if (idx4 >= N_NODES * 32) return;
    int r = idx4 >> 5;
    int c = (idx4 & 31) * 4;
    const float invN = 1.0f / (float)N_NODES;
    float4 v = *(const float4*)(pre + (size_t)r * 128 + c);
    float vv[4] = {v.x, v.y, v.z, v.w};
    float hv[4];
#pragma unroll
    for (int qd = 0; qd < 4; qd++) {
        float mu  = stats[c + qd] * invN;
        float var = stats[128 + c + qd] * invN - mu * mu;
        float inv = rsqrtf(var + BN_EPS);
        float bn  = (vv[qd] - mu) * inv * gamma[c + qd] + beta[c + qd];
        hv[qd] = bn > 0.0f ? bn : 0.0f;
    }
    size_t o0 = (size_t)r * 256 + c;
    // relu(bn) half
    {
        __nv_bfloat16 h0 = __float2bfloat16(hv[0]), h1 = __float2bfloat16(hv[1]);
        __nv_bfloat16 h2 = __float2bfloat16(hv[2]), h3 = __float2bfloat16(hv[3]);
        __nv_bfloat162 a = {h0, h1}, b = {h2, h3};
        *(uint2*)(xhi + o0) = make_uint2(*(uint32_t*)&a, *(uint32_t*)&b);
        __nv_bfloat162 la = {__float2bfloat16(hv[0] - __bfloat162float(h0)),
                             __float2bfloat16(hv[1] - __bfloat162float(h1))};
        __nv_bfloat162 lb = {__float2bfloat16(hv[2] - __bfloat162float(h2)),
                             __float2bfloat16(hv[3] - __bfloat162float(h3))};
        *(uint2*)(xlo + o0) = make_uint2(*(uint32_t*)&la, *(uint32_t*)&lb);
    }
    // skip half (raw pre)
    {
        __nv_bfloat16 h0 = __float2bfloat16(vv[0]), h1 = __float2bfloat16(vv[1]);
        __nv_bfloat16 h2 = __float2bfloat16(vv[2]), h3 = __float2bfloat16(vv[3]);
        __nv_bfloat162 a = {h0, h1}, b = {h2, h3};
        *(uint2*)(xhi + o0 + 128) = make_uint2(*(uint32_t*)&a, *(uint32_t*)&b);
        __nv_bfloat162 la = {__float2bfloat16(vv[0] - __bfloat162float(h0)),
                             __float2bfloat16(vv[1] - __bfloat162float(h1))};
        __nv_bfloat162 lb = {__float2bfloat16(vv[2] - __bfloat162float(h2)),
                             __float2bfloat16(vv[3] - __bfloat162float(h3))};
        *(uint2*)(xlo + o0 + 128) = make_uint2(*(uint32_t*)&la, *(uint32_t*)&lb);
    }
    // zero pre for next layer's aggregation
    *(float4*)(prez + (size_t)r * 128 + c) = make_float4(0.f, 0.f, 0.f, 0.f);
}

// ---------------- launch ------------------------------------------------------
extern "C" void kernel_launch(void* const* d_in, const int* in_sizes, int n_in,
                              void* d_out, int out_size) {
    const float* x      = (const float*)d_in[0];
    const int*   src    = (const int*)  d_in[1];
    const int*   dst    = (const int*)  d_in[2];
    const float* ew     = (const float*)d_in[3];
    const float* W0     = (const float*)d_in[4];
    const float* W1     = (const float*)d_in[5];
    const float* W2     = (const float*)d_in[6];
    const float* gamma0 = (const float*)d_in[7];
    const float* beta0  = (const float*)d_in[8];
    const float* gamma1 = (const float*)d_in[9];
    const float* beta1  = (const float*)d_in[10];
    float* out = (float*)d_out;

    __nv_bfloat16 *xhi, *xlo, *whi, *wlo;
    float *proj, *pre, *stats;
    cudaGetSymbolAddress((void**)&xhi,   g_xhi);
    cudaGetSymbolAddress((void**)&xlo,   g_xlo);
    cudaGetSymbolAddress((void**)&whi,   g_whi);
    cudaGetSymbolAddress((void**)&wlo,   g_wlo);
    cudaGetSymbolAddress((void**)&proj,  g_proj);
    cudaGetSymbolAddress((void**)&pre,   g_pre);
    cudaGetSymbolAddress((void**)&stats, g_stats);

    const int smem128 = 2 * (256 + 2 * 128) * 96;   // 98304
    const int smem32  = 2 * (256 + 2 * 32)  * 96;   // 61440
    cudaFuncSetAttribute(gemm_mma2<128>, cudaFuncAttributeMaxDynamicSharedMemorySize, smem128);
    cudaFuncSetAttribute(gemm_mma2<32>,  cudaFuncAttributeMaxDynamicSharedMemorySize, smem32);

    const int nX4    = N_NODES * 256 / 4;
    const int nPre4  = N_NODES * 128 / 4;
    const int nOut4  = N_NODES * 32 / 4;
    const int aggB128 = (N_EDGES * 32) / 256;
    const int aggB32  = (N_EDGES * 8)  / 256;
    const int bnBlocks = (N_NODES * 32 + 255) / 256;
    const int mTiles = (N_NODES + 127) / 128;    // 391

    // ---- layer 0 ----
    convert_x4<<<(nX4 + 255) / 256, 256>>>(x, xhi, xlo, nX4);
    convert_w<<<(128 * 256 + 255) / 256, 256>>>(W0, whi, wlo, 128);
    zero4<<<(nPre4 + 255) / 256, 256>>>((float4*)pre, nPre4);
    zero_f<<<1, 256>>>(stats, 256);
    gemm_mma2<128><<<mTiles, 256, smem128>>>(xhi, xlo, whi, wlo, proj, N_NODES);
    aggregate128<<<aggB128, 256>>>(proj, src, dst, ew, pre);
    bn_stats2<<<256, 256>>>(pre, stats);
    bn_apply_concat4<<<bnBlocks, 256>>>(pre, stats, gamma0, beta0, xhi, xlo, pre);

    // ---- layer 1 ----  (pre was zeroed by bn_apply_concat4 above)
    convert_w<<<(128 * 256 + 255) / 256, 256>>>(W1, whi, wlo, 128);
    zero_f<<<1, 256>>>(stats, 256);
    gemm_mma2<128><<<mTiles, 256, smem128>>>(xhi, xlo, whi, wlo, proj, N_NODES);
    aggregate128<<<aggB128, 256>>>(proj, src, dst, ew, pre);
    bn_stats2<<<256, 256>>>(pre, stats);
    bn_apply_concat4<<<bnBlocks, 256>>>(pre, stats, gamma1, beta1, xhi, xlo, pre);

    // ---- output layer (N=32) ----
    convert_w<<<(32 * 256 + 255) / 256, 256>>>(W2, whi, wlo, 32);
    gemm_mma2<32><<<mTiles, 256, smem32>>>(xhi, xlo, whi, wlo, proj, N_NODES);
    zero4<<<(nOut4 + 255) / 256, 256>>>((float4*)out, nOut4);
    aggregate32<<<aggB32, 256>>>(proj, src, dst, ew, out);
}

// round 5
// speedup vs baseline: 2.0667x; 1.2297x over previous
#include <cuda_runtime.h>
#include <cuda_bf16.h>
#include <cstdint>
#include <cstddef>

#define N_NODES 50000
#define N_EDGES 800000
#define BN_EPS  1e-5f

// ---------------- scratch (static device globals; allocation-free) ----------
__device__ __nv_bfloat16 g_xhi[(size_t)N_NODES * 256];
__device__ __nv_bfloat16 g_xlo[(size_t)N_NODES * 256];
__device__ __nv_bfloat16 g_whi[256 * 128];
__device__ __nv_bfloat16 g_wlo[256 * 128];
__device__ float g_proj[(size_t)N_NODES * 128];
__device__ float g_pre [(size_t)N_NODES * 128];
__device__ float g_stats[512];                 // layer0: [0:256), layer1: [256:512)
__device__ int   g_deg[N_NODES];
__device__ int   g_cur[N_NODES];
__device__ int   g_off[N_NODES + 1];
__device__ int2  g_erec[N_EDGES];              // (src, w as bits), grouped by dst

// ---------------- asm helpers ------------------------------------------------
__device__ __forceinline__ void mma16816(float* d, const uint32_t* a, const uint32_t* b) {
    asm volatile(
        "mma.sync.aligned.m16n8k16.row.col.f32.bf16.bf16.f32 "
        "{%0,%1,%2,%3}, {%4,%5,%6,%7}, {%8,%9}, {%0,%1,%2,%3};"
        : "+f"(d[0]), "+f"(d[1]), "+f"(d[2]), "+f"(d[3])
        : "r"(a[0]), "r"(a[1]), "r"(a[2]), "r"(a[3]), "r"(b[0]), "r"(b[1]));
}
__device__ __forceinline__ void ldsm4(uint32_t* r, uint32_t a) {
    asm volatile("ldmatrix.sync.aligned.m8n8.x4.shared.b16 {%0,%1,%2,%3}, [%4];"
                 : "=r"(r[0]), "=r"(r[1]), "=r"(r[2]), "=r"(r[3]) : "r"(a));
}
__device__ __forceinline__ uint32_t smem_u32(const void* p) {
    uint32_t a;
    asm("{ .reg .u64 t; cvta.to.shared.u64 t, %1; cvt.u32.u64 %0, t; }" : "=r"(a) : "l"(p));
    return a;
}
__device__ __forceinline__ void cpasync16(uint32_t dst, const void* src, int src_sz) {
    asm volatile("cp.async.ca.shared.global [%0], [%1], 16, %2;"
                 :: "r"(dst), "l"(src), "r"(src_sz));
}
#define CP_COMMIT() asm volatile("cp.async.commit_group;" ::: "memory")
__device__ __forceinline__ void redg_v4(float* p, float4 v) {
    asm volatile("red.global.add.v4.f32 [%0], {%1,%2,%3,%4};"
                 :: "l"(p), "f"(v.x), "f"(v.y), "f"(v.z), "f"(v.w) : "memory");
}

// ---------------- CSR build ---------------------------------------------------
__global__ __launch_bounds__(256)
void csr_zero(int* __restrict__ deg, float* __restrict__ stats) {
    int i = blockIdx.x * blockDim.x + threadIdx.x;
    if (i < N_NODES) deg[i] = 0;
    if (i < 512) stats[i] = 0.0f;
}
__global__ __launch_bounds__(256)
void csr_hist(const int* __restrict__ dst, int* __restrict__ deg) {
    int e = blockIdx.x * blockDim.x + threadIdx.x;
    if (e < N_EDGES) atomicAdd(&deg[dst[e]], 1);
}
__global__ __launch_bounds__(1024)
void csr_scan(const int* __restrict__ deg, int* __restrict__ off, int* __restrict__ cur) {
    __shared__ int wsum[32];
    const int t = threadIdx.x;                 // 0..1023
    const int base = t * 49;
    int s = 0;
#pragma unroll 7
    for (int k = 0; k < 49; k++) {
        int idx = base + k;
        if (idx < N_NODES) s += deg[idx];
    }
    int v = s;
#pragma unroll
    for (int o = 1; o < 32; o <<= 1) {
        int u = __shfl_up_sync(0xFFFFFFFFu, v, o);
        if ((t & 31) >= o) v += u;
    }
    if ((t & 31) == 31) wsum[t >> 5] = v;
    __syncthreads();
    if (t < 32) {
        int w = wsum[t];
#pragma unroll
        for (int o = 1; o < 32; o <<= 1) {
            int u = __shfl_up_sync(0xFFFFFFFFu, w, o);
            if (t >= o) w += u;
        }
        wsum[t] = w;
    }
    __syncthreads();
    int run = v - s + ((t >= 32) ? wsum[(t >> 5) - 1] : 0);
#pragma unroll 7
    for (int k = 0; k < 49; k++) {
        int idx = base + k;
        if (idx < N_NODES) {
            off[idx] = run;
            cur[idx] = run;
            run += deg[idx];
        }
    }
    if (t == 1023) off[N_NODES] = run;
}
__global__ __launch_bounds__(256)
void csr_fill(const int* __restrict__ src, const int* __restrict__ dst,
              const float* __restrict__ w, int* __restrict__ cur, int2* __restrict__ erec) {
    int e = blockIdx.x * blockDim.x + threadIdx.x;
    if (e >= N_EDGES) return;
    int pos = atomicAdd(&cur[dst[e]], 1);
    erec[pos] = make_int2(src[e], __float_as_int(w[e]));
}

// ---------------- CSR aggregation ---------------------------------------------
// width 128: one warp per node, lane holds float4 (4 cols)
__global__ __launch_bounds__(256)
void agg_csr128(const float* __restrict__ h, const int* __restrict__ off,
                const int2* __restrict__ erec, float* __restrict__ out) {
    int n = blockIdx.x * 8 + (threadIdx.x >> 5);
    int lane = threadIdx.x & 31;
    if (n >= N_NODES) return;
    int i = off[n], end = off[n + 1];
    const float4* h4 = (const float4*)h;
    float4 acc = make_float4(0.f, 0.f, 0.f, 0.f);
    for (; i + 1 < end; i += 2) {
        int2 r0 = erec[i], r1 = erec[i + 1];
        float w0 = __int_as_float(r0.y), w1 = __int_as_float(r1.y);
        float4 v0 = h4[(size_t)r0.x * 32 + lane];
        float4 v1 = h4[(size_t)r1.x * 32 + lane];
        acc.x += w0 * v0.x + w1 * v1.x;
        acc.y += w0 * v0.y + w1 * v1.y;
        acc.z += w0 * v0.z + w1 * v1.z;
        acc.w += w0 * v0.w + w1 * v1.w;
    }
    if (i < end) {
        int2 r0 = erec[i];
        float w0 = __int_as_float(r0.y);
        float4 v0 = h4[(size_t)r0.x * 32 + lane];
        acc.x += w0 * v0.x; acc.y += w0 * v0.y;
        acc.z += w0 * v0.z; acc.w += w0 * v0.w;
    }
    ((float4*)out)[(size_t)n * 32 + lane] = acc;
}

// width 32: 8 lanes per node, lane holds float4
__global__ __launch_bounds__(256)
void agg_csr32(const float* __restrict__ h, const int* __restrict__ off,
               const int2* __restrict__ erec, float* __restrict__ out) {
    int gid = blockIdx.x * blockDim.x + threadIdx.x;
    int n = gid >> 3;
    int sl = gid & 7;
    if (n >= N_NODES) return;
    int i = off[n], end = off[n + 1];
    const float4* h4 = (const float4*)h;
    float4 acc = make_float4(0.f, 0.f, 0.f, 0.f);
    for (; i + 1 < end; i += 2) {
        int2 r0 = erec[i], r1 = erec[i + 1];
        float w0 = __int_as_float(r0.y), w1 = __int_as_float(r1.y);
        float4 v0 = h4[(size_t)r0.x * 8 + sl];
        float4 v1 = h4[(size_t)r1.x * 8 + sl];
        acc.x += w0 * v0.x + w1 * v1.x;
        acc.y += w0 * v0.y + w1 * v1.y;
        acc.z += w0 * v0.z + w1 * v1.z;
        acc.w += w0 * v0.w + w1 * v1.w;
    }
    if (i < end) {
        int2 r0 = erec[i];
        float w0 = __int_as_float(r0.y);
        float4 v0 = h4[(size_t)r0.x * 8 + sl];
        acc.x += w0 * v0.x; acc.y += w0 * v0.y;
        acc.z += w0 * v0.z; acc.w += w0 * v0.w;
    }
    ((float4*)out)[(size_t)n * 8 + sl] = acc;
}

// ---------------- conversion kernels -------------------------------------------
__global__ __launch_bounds__(256)
void convert_x4(const float* __restrict__ x, __nv_bfloat16* __restrict__ hi,
                __nv_bfloat16* __restrict__ lo, int n4) {
    int i = blockIdx.x * blockDim.x + threadIdx.x;
    if (i >= n4) return;
    float4 v = ((const float4*)x)[i];
    __nv_bfloat16 h0 = __float2bfloat16(v.x), h1 = __float2bfloat16(v.y);
    __nv_bfloat16 h2 = __float2bfloat16(v.z), h3 = __float2bfloat16(v.w);
    __nv_bfloat162 a = {h0, h1}, b = {h2, h3};
    ((uint2*)hi)[i] = make_uint2(*(uint32_t*)&a, *(uint32_t*)&b);
    __nv_bfloat162 c = {__float2bfloat16(v.x - __bfloat162float(h0)),
                        __float2bfloat16(v.y - __bfloat162float(h1))};
    __nv_bfloat162 d = {__float2bfloat16(v.z - __bfloat162float(h2)),
                        __float2bfloat16(v.w - __bfloat162float(h3))};
    ((uint2*)lo)[i] = make_uint2(*(uint32_t*)&c, *(uint32_t*)&d);
}
__global__ __launch_bounds__(256)
void convert_w(const float* __restrict__ W, __nv_bfloat16* __restrict__ hi,
               __nv_bfloat16* __restrict__ lo, int N) {
    int i = blockIdx.x * blockDim.x + threadIdx.x;
    if (i >= N * 256) return;
    int n = i >> 8, k = i & 255;
    float v = W[(size_t)k * N + n];
    __nv_bfloat16 h = __float2bfloat16(v);
    hi[i] = h;
    lo[i] = __float2bfloat16(v - __bfloat162float(h));
}

// ---------------- pipelined ldmatrix GEMM --------------------------------------
// C[M,NT] = A[M,256] @ Wt[NT,256]^T. CTA 128xNT, 8 warps (4m x 2n), BK=32.
// smem row stride 80B: 80*r mod 128 all distinct for r=0..7 -> conflict-free.
template <int NT>
__device__ __forceinline__ void gload(uint32_t sbase, const uint4* Ahi4, const uint4* Alo4,
                                      const uint4* Bhi4, const uint4* Blo4,
                                      int m0, int M, int ch, int tid) {
    const uint32_t sAhi = sbase;
    const uint32_t sAlo = sbase + 128 * 80;
    const uint32_t sBhi = sbase + 256 * 80;
    const uint32_t sBlo = sbase + 256 * 80 + NT * 80;
#pragma unroll
    for (int j = 0; j < 2; j++) {               // A: 128 rows x 4 uint4
        int i   = tid + j * 256;
        int row = i >> 2, c4 = i & 3;
        int gr  = m0 + row;
        int ok  = (gr < M) ? 16 : 0;
        size_t g = (size_t)(ok ? gr : 0) * 32 + ch * 4 + c4;
        cpasync16(sAhi + row * 80 + c4 * 16, Ahi4 + g, ok);
        cpasync16(sAlo + row * 80 + c4 * 16, Alo4 + g, ok);
    }
#pragma unroll
    for (int j = 0; j < (NT * 4 + 255) / 256; j++) {
        int i = tid + j * 256;
        if (i < NT * 4) {
            int row = i >> 2, c4 = i & 3;
            size_t g = (size_t)row * 32 + ch * 4 + c4;
            cpasync16(sBhi + row * 80 + c4 * 16, Bhi4 + g, 16);
            cpasync16(sBlo + row * 80 + c4 * 16, Blo4 + g, 16);
        }
    }
}

template <int NT>
__global__ __launch_bounds__(256, 2)
void gemm_mma3(const __nv_bfloat16* __restrict__ Ahi, const __nv_bfloat16* __restrict__ Alo,
               const __nv_bfloat16* __restrict__ Bhi, const __nv_bfloat16* __restrict__ Blo,
               float* __restrict__ C, int M) {
    constexpr int WNT   = NT / 16;
    constexpr int STAGE = (256 + 2 * NT) * 80;
    extern __shared__ char sm[];
    const uint32_t smu = smem_u32(sm);

    const int tid  = threadIdx.x;
    const int wid  = tid >> 5;
    const int lane = tid & 31;
    const int wm   = wid & 3;
    const int wn   = wid >> 2;
    const int m0   = blockIdx.x * 128;
    const int r    = lane >> 2;
    const int c2   = (lane & 3) * 2;

    // ldmatrix per-lane address components
    const uint32_t aOff = (uint32_t)(lane & 15) * 80 + ((lane & 16) ? 16u : 0u);
    const uint32_t bOff = (uint32_t)((lane & 7) + ((lane & 16) ? 8 : 0)) * 80 +
                          ((lane & 8) ? 16u : 0u);

    const uint4* Ahi4 = (const uint4*)Ahi;
    const uint4* Alo4 = (const uint4*)Alo;
    const uint4* Bhi4 = (const uint4*)Bhi;
    const uint4* Blo4 = (const uint4*)Blo;

    float acc[2][WNT][4];
#pragma unroll
    for (int mt = 0; mt < 2; mt++)
#pragma unroll
        for (int j = 0; j < WNT; j++)
#pragma unroll
            for (int q = 0; q < 4; q++) acc[mt][j][q] = 0.0f;

    gload<NT>(smu, Ahi4, Alo4, Bhi4, Blo4, m0, M, 0, tid);
    CP_COMMIT();

    for (int ch = 0; ch < 8; ch++) {
        if (ch < 7) {
            gload<NT>(smu + ((ch + 1) & 1) * STAGE, Ahi4, Alo4, Bhi4, Blo4, m0, M, ch + 1, tid);
            CP_COMMIT();
            asm volatile("cp.async.wait_group 1;" ::: "memory");
        } else {
            asm volatile("cp.async.wait_group 0;" ::: "memory");
        }
        __syncthreads();

        const uint32_t st = smu + (ch & 1) * STAGE;

#pragma unroll
        for (int ks = 0; ks < 2; ks++) {
            const uint32_t k0b = ks * 32;
            uint32_t ah[2][4], al[2][4];
#pragma unroll
            for (int mt = 0; mt < 2; mt++) {
                uint32_t rowb = (uint32_t)(wm * 32 + mt * 16) * 80;
                ldsm4(ah[mt], st + rowb + aOff + k0b);
                ldsm4(al[mt], st + 128 * 80 + rowb + aOff + k0b);
            }
#pragma unroll
            for (int p = 0; p < WNT / 2; p++) {
                uint32_t n0b = (uint32_t)(wn * (NT / 2) + p * 16) * 80;
                uint32_t ba = st + 256 * 80 + n0b + bOff + k0b;
                uint32_t bh4[4], bl4[4];
                ldsm4(bh4, ba);
                ldsm4(bl4, ba + NT * 80);
#pragma unroll
                for (int jj = 0; jj < 2; jj++) {
                    int j = p * 2 + jj;
#pragma unroll
                    for (int mt = 0; mt < 2; mt++) {
                        mma16816(acc[mt][j], ah[mt], bh4 + jj * 2);
                        mma16816(acc[mt][j], ah[mt], bl4 + jj * 2);
                        mma16816(acc[mt][j], al[mt], bh4 + jj * 2);
                    }
                }
            }
        }
        __syncthreads();
    }

#pragma unroll
    for (int mt = 0; mt < 2; mt++) {
        int row0 = m0 + wm * 32 + mt * 16 + r;
#pragma unroll
        for (int j = 0; j < WNT; j++) {
            int col = wn * (NT / 2) + j * 8 + c2;
            if (row0 < M)
                *(float2*)&C[(size_t)row0 * NT + col] = make_float2(acc[mt][j][0], acc[mt][j][1]);
            if (row0 + 8 < M)
                *(float2*)&C[(size_t)(row0 + 8) * NT + col] = make_float2(acc[mt][j][2], acc[mt][j][3]);
        }
    }
}

// ---------------- BN stats (vectorized, block-reduced) --------------------------
__global__ __launch_bounds__(256)
void bn_stats2(const float* __restrict__ pre, float* __restrict__ stats) {
    int tid = threadIdx.x;
    int cg  = tid & 31;
    int rg  = tid >> 5;
    int c   = cg * 4;
    float4 s = make_float4(0.f, 0.f, 0.f, 0.f);
    float4 q = make_float4(0.f, 0.f, 0.f, 0.f);
    for (int r = blockIdx.x * 8 + rg; r < N_NODES; r += gridDim.x * 8) {
        float4 v = *(const float4*)(pre + (size_t)r * 128 + c);
        s.x += v.x; s.y += v.y; s.z += v.z; s.w += v.w;
        q.x += v.x * v.x; q.y += v.y * v.y; q.z += v.z * v.z; q.w += v.w * v.w;
    }
    __shared__ float shS[8][128], shQ[8][128];
    *(float4*)&shS[rg][c] = s;
    *(float4*)&shQ[rg][c] = q;
    __syncthreads();
    if (tid < 32) {
        int cc = tid * 4;
        float4 S = make_float4(0.f, 0.f, 0.f, 0.f);
        float4 Q = make_float4(0.f, 0.f, 0.f, 0.f);
#pragma unroll
        for (int g = 0; g < 8; g++) {
            float4 a = *(float4*)&shS[g][cc];
            float4 b = *(float4*)&shQ[g][cc];
            S.x += a.x; S.y += a.y; S.z += a.z; S.w += a.w;
            Q.x += b.x; Q.y += b.y; Q.z += b.z; Q.w += b.w;
        }
        redg_v4(stats + cc, S);
        redg_v4(stats + 128 + cc, Q);
    }
}

// ---------------- BN apply + ReLU + concat -> bf16 hi/lo ------------------------
__global__ __launch_bounds__(256)
void bn_apply_concat4(const float* __restrict__ pre, const float* __restrict__ stats,
                      const float* __restrict__ gamma, const float* __restrict__ beta,
                      __nv_bfloat16* __restrict__ xhi, __nv_bfloat16* __restrict__ xlo) {
    int idx4 = blockIdx.x * blockDim.x + threadIdx.x;
    if (idx4 >= N_NODES * 32) return;
    int r = idx4 >> 5;
    int c = (idx4 & 31) * 4;
    const float invN = 1.0f / (float)N_NODES;
    float4 v = *(const float4*)(pre + (size_t)r * 128 + c);
    float vv[4] = {v.x, v.y, v.z, v.w};
    float hv[4];
#pragma unroll
    for (int qd = 0; qd < 4; qd++) {
        float mu  = stats[c + qd] * invN;
        float var = stats[128 + c + qd] * invN - mu * mu;
        float inv = rsqrtf(var + BN_EPS);
        float bn  = (vv[qd] - mu) * inv * gamma[c + qd] + beta[c + qd];
        hv[qd] = bn > 0.0f ? bn : 0.0f;
    }
    size_t o0 = (size_t)r * 256 + c;
    {
        __nv_bfloat16 h0 = __float2bfloat16(hv[0]), h1 = __float2bfloat16(hv[1]);
        __nv_bfloat16 h2 = __float2bfloat16(hv[2]), h3 = __float2bfloat16(hv[3]);
        __nv_bfloat162 a = {h0, h1}, b = {h2, h3};
        *(uint2*)(xhi + o0) = make_uint2(*(uint32_t*)&a, *(uint32_t*)&b);
        __nv_bfloat162 la = {__float2bfloat16(hv[0] - __bfloat162float(h0)),
                             __float2bfloat16(hv[1] - __bfloat162float(h1))};
        __nv_bfloat162 lb = {__float2bfloat16(hv[2] - __bfloat162float(h2)),
                             __float2bfloat16(hv[3] - __bfloat162float(h3))};
        *(uint2*)(xlo + o0) = make_uint2(*(uint32_t*)&la, *(uint32_t*)&lb);
    }
    {
        __nv_bfloat16 h0 = __float2bfloat16(vv[0]), h1 = __float2bfloat16(vv[1]);
        __nv_bfloat16 h2 = __float2bfloat16(vv[2]), h3 = __float2bfloat16(vv[3]);
        __nv_bfloat162 a = {h0, h1}, b = {h2, h3};
        *(uint2*)(xhi + o0 + 128) = make_uint2(*(uint32_t*)&a, *(uint32_t*)&b);
        __nv_bfloat162 la = {__float2bfloat16(vv[0] - __bfloat162float(h0)),
                             __float2bfloat16(vv[1] - __bfloat162float(h1))};
        __nv_bfloat162 lb = {__float2bfloat16(vv[2] - __bfloat162float(h2)),
                             __float2bfloat16(vv[3] - __bfloat162float(h3))};
        *(uint2*)(xlo + o0 + 128) = make_uint2(*(uint32_t*)&la, *(uint32_t*)&lb);
    }
}

// ---------------- launch ---------------------------------------------------------
extern "C" void kernel_launch(void* const* d_in, const int* in_sizes, int n_in,
                              void* d_out, int out_size) {
    const float* x      = (const float*)d_in[0];
    const int*   src    = (const int*)  d_in[1];
    const int*   dst    = (const int*)  d_in[2];
    const float* ew     = (const float*)d_in[3];
    const float* W0     = (const float*)d_in[4];
    const float* W1     = (const float*)d_in[5];
    const float* W2     = (const float*)d_in[6];
    const float* gamma0 = (const float*)d_in[7];
    const float* beta0  = (const float*)d_in[8];
    const float* gamma1 = (const float*)d_in[9];
    const float* beta1  = (const float*)d_in[10];
    float* out = (float*)d_out;

    __nv_bfloat16 *xhi, *xlo, *whi, *wlo;
    float *proj, *pre, *stats;
    int *deg, *cur, *off;
    int2 *erec;
    cudaGetSymbolAddress((void**)&xhi,   g_xhi);
    cudaGetSymbolAddress((void**)&xlo,   g_xlo);
    cudaGetSymbolAddress((void**)&whi,   g_whi);
    cudaGetSymbolAddress((void**)&wlo,   g_wlo);
    cudaGetSymbolAddress((void**)&proj,  g_proj);
    cudaGetSymbolAddress((void**)&pre,   g_pre);
    cudaGetSymbolAddress((void**)&stats, g_stats);
    cudaGetSymbolAddress((void**)&deg,   g_deg);
    cudaGetSymbolAddress((void**)&cur,   g_cur);
    cudaGetSymbolAddress((void**)&off,   g_off);
    cudaGetSymbolAddress((void**)&erec,  g_erec);

    const int smem128 = 2 * (256 + 2 * 128) * 80;   // 81920
    const int smem32  = 2 * (256 + 2 * 32)  * 80;   // 51200
    cudaFuncSetAttribute(gemm_mma3<128>, cudaFuncAttributeMaxDynamicSharedMemorySize, smem128);
    cudaFuncSetAttribute(gemm_mma3<32>,  cudaFuncAttributeMaxDynamicSharedMemorySize, smem32);

    const int nX4      = N_NODES * 256 / 4;
    const int bnBlocks = (N_NODES * 32 + 255) / 256;
    const int mTiles   = (N_NODES + 127) / 128;           // 391
    const int edgeB    = (N_EDGES + 255) / 256;            // 3125
    const int aggB128  = (N_NODES + 7) / 8;                // 6250
    const int aggB32   = (N_NODES * 8 + 255) / 256;        // 1563

    // ---- CSR build (reused by all 3 aggregations) + zero stats ----
    csr_zero<<<(N_NODES + 255) / 256, 256>>>(deg, stats);
    csr_hist<<<edgeB, 256>>>(dst, deg);
    csr_scan<<<1, 1024>>>(deg, off, cur);
    csr_fill<<<edgeB, 256>>>(src, dst, ew, cur, erec);

    // ---- layer 0 ----
    convert_x4<<<(nX4 + 255) / 256, 256>>>(x, xhi, xlo, nX4);
    convert_w<<<(128 * 256 + 255) / 256, 256>>>(W0, whi, wlo, 128);
    gemm_mma3<128><<<mTiles, 256, smem128>>>(xhi, xlo, whi, wlo, proj, N_NODES);
    agg_csr128<<<aggB128, 256>>>(proj, off, erec, pre);
    bn_stats2<<<256, 256>>>(pre, stats);
    bn_apply_concat4<<<bnBlocks, 256>>>(pre, stats, gamma0, beta0, xhi, xlo);

    // ---- layer 1 ----
    convert_w<<<(128 * 256 + 255) / 256, 256>>>(W1, whi, wlo, 128);
    gemm_mma3<128><<<mTiles, 256, smem128>>>(xhi, xlo, whi, wlo, proj, N_NODES);
    agg_csr128<<<aggB128, 256>>>(proj, off, erec, pre);
    bn_stats2<<<256, 256>>>(pre, stats + 256);
    bn_apply_concat4<<<bnBlocks, 256>>>(pre, stats + 256, gamma1, beta1, xhi, xlo);

    // ---- output layer (N=32) ----
    convert_w<<<(32 * 256 + 255) / 256, 256>>>(W2, whi, wlo, 32);
    gemm_mma3<32><<<mTiles, 256, smem32>>>(xhi, xlo, whi, wlo, proj, N_NODES);
    agg_csr32<<<aggB32, 256>>>(proj, off, erec, out);
}